// round 1
// baseline (speedup 1.0000x reference)
#include <cuda_runtime.h>
#include <math.h>

#define EPS_V 1e-6f
#define MARGIN_V 1.0f

// Scratch (allocation-free rule: __device__ globals)
__device__ float g_dap[64];           // d_ap per positive (P small)
__device__ float g_partials[65536];   // per-block partial sums (kernel B)

// ---------------------------------------------------------------------------
// Kernel A: one block per positive sample. Computes d_ap[p] = ||a - pos_p + eps||
// ---------------------------------------------------------------------------
__global__ void dap_kernel(const float* __restrict__ anchor,
                           const float* __restrict__ pos,
                           int D) {
    const int p = blockIdx.x;
    const float* __restrict__ x = pos + (size_t)p * D;
    float ss = 0.0f;
    for (int i = threadIdx.x; i < D; i += blockDim.x) {
        float d = anchor[i] - x[i] + EPS_V;
        ss = fmaf(d, d, ss);
    }
    // block reduce
    __shared__ float s[32];
    int lane = threadIdx.x & 31;
    int wid  = threadIdx.x >> 5;
    #pragma unroll
    for (int off = 16; off > 0; off >>= 1)
        ss += __shfl_xor_sync(0xffffffffu, ss, off);
    if (lane == 0) s[wid] = ss;
    __syncthreads();
    if (threadIdx.x == 0) {
        float tot = 0.0f;
        int nw = (blockDim.x + 31) >> 5;
        for (int w = 0; w < nw; ++w) tot += s[w];
        g_dap[p] = sqrtf(tot);
    }
}

// ---------------------------------------------------------------------------
// Kernel B: one warp per negative row. 8 warps / block.
// Anchor staged in dynamic smem. Per-block partial sum -> g_partials.
// ---------------------------------------------------------------------------
__global__ void __launch_bounds__(256) dan_kernel(
        const float* __restrict__ anchor,
        const float* __restrict__ neg,
        int D, int R, int P) {
    extern __shared__ float4 s_a4[];           // D/4 float4 of anchor
    __shared__ float s_warp[8];

    const int D4   = D >> 2;
    const int lane = threadIdx.x & 31;
    const int wid  = threadIdx.x >> 5;

    // stage anchor into smem (vectorized)
    const float4* __restrict__ a4 = (const float4*)anchor;
    for (int i = threadIdx.x; i < D4; i += blockDim.x) s_a4[i] = a4[i];
    __syncthreads();

    const int row = blockIdx.x * 8 + wid;
    float term = 0.0f;
    if (row < R) {
        const float4* __restrict__ x4 = (const float4*)(neg + (size_t)row * D);
        float ss = 0.0f;
        #pragma unroll 4
        for (int i = lane; i < D4; i += 32) {
            float4 x = x4[i];
            float4 a = s_a4[i];
            float d0 = a.x - x.x + EPS_V;
            float d1 = a.y - x.y + EPS_V;
            float d2 = a.z - x.z + EPS_V;
            float d3 = a.w - x.w + EPS_V;
            ss = fmaf(d0, d0, ss);
            ss = fmaf(d1, d1, ss);
            ss = fmaf(d2, d2, ss);
            ss = fmaf(d3, d3, ss);
        }
        #pragma unroll
        for (int off = 16; off > 0; off >>= 1)
            ss += __shfl_xor_sync(0xffffffffu, ss, off);
        float dan = sqrtf(ss);
        float t = g_dap[row % P] - dan + MARGIN_V;
        term = t > 0.0f ? t : 0.0f;
    }
    if (lane == 0) s_warp[wid] = term;
    __syncthreads();
    if (threadIdx.x == 0) {
        float tot = 0.0f;
        #pragma unroll
        for (int w = 0; w < 8; ++w) tot += s_warp[w];
        g_partials[blockIdx.x] = tot;
    }
}

// ---------------------------------------------------------------------------
// Kernel C: deterministic final reduce of per-block partials -> d_out[0]
// ---------------------------------------------------------------------------
__global__ void __launch_bounds__(1024) reduce_kernel(float* __restrict__ out, int nPartials) {
    __shared__ float s[32];
    float acc = 0.0f;
    for (int i = threadIdx.x; i < nPartials; i += blockDim.x)
        acc += g_partials[i];
    int lane = threadIdx.x & 31;
    int wid  = threadIdx.x >> 5;
    #pragma unroll
    for (int off = 16; off > 0; off >>= 1)
        acc += __shfl_xor_sync(0xffffffffu, acc, off);
    if (lane == 0) s[wid] = acc;
    __syncthreads();
    if (threadIdx.x == 0) {
        float tot = 0.0f;
        for (int w = 0; w < 32; ++w) tot += s[w];
        out[0] = tot;
    }
}

// ---------------------------------------------------------------------------
extern "C" void kernel_launch(void* const* d_in, const int* in_sizes, int n_in,
                              void* d_out, int out_size) {
    const float* anchor = (const float*)d_in[0];
    const float* pos    = (const float*)d_in[1];
    const float* neg    = (const float*)d_in[2];
    float* out          = (float*)d_out;

    const int D = in_sizes[0];            // 2400
    const int P = in_sizes[1] / D;        // 5
    const int N = in_sizes[2] / D;        // 50000
    const int C = N / P;                  // 10000
    const int R = C * P;                  // rows actually used

    // Kernel A: d_ap
    dap_kernel<<<P, 256>>>(anchor, pos, D);

    // Kernel B: one warp per row, 8 warps per block
    const int blocksB = (R + 7) / 8;      // 6250 for the given shape
    const size_t smem = (size_t)(D >> 2) * sizeof(float4);
    dan_kernel<<<blocksB, 256, smem>>>(anchor, neg, D, R, P);

    // Kernel C: final deterministic reduce
    reduce_kernel<<<1, 1024>>>(out, blocksB);
}

// round 2
// speedup vs baseline: 1.0129x; 1.0129x over previous
#include <cuda_runtime.h>
#include <math.h>

#define EPS_V 1e-6f
#define MARGIN_V 1.0f

// Scratch (allocation-free rule: __device__ globals)
__device__ float g_dap[64];           // d_ap per positive (P small)
__device__ float g_partials[65536];   // per-block partial sums (kernel B)

// ---------------------------------------------------------------------------
// Kernel A: one block per positive sample. Computes d_ap[p] = ||a - pos_p + eps||
// ---------------------------------------------------------------------------
__global__ void dap_kernel(const float* __restrict__ anchor,
                           const float* __restrict__ pos,
                           int D) {
    const int p = blockIdx.x;
    const float* __restrict__ x = pos + (size_t)p * D;
    float ss = 0.0f;
    for (int i = threadIdx.x; i < D; i += blockDim.x) {
        float d = anchor[i] - x[i] + EPS_V;
        ss = fmaf(d, d, ss);
    }
    // block reduce
    __shared__ float s[32];
    int lane = threadIdx.x & 31;
    int wid  = threadIdx.x >> 5;
    #pragma unroll
    for (int off = 16; off > 0; off >>= 1)
        ss += __shfl_xor_sync(0xffffffffu, ss, off);
    if (lane == 0) s[wid] = ss;
    __syncthreads();
    if (threadIdx.x == 0) {
        float tot = 0.0f;
        int nw = (blockDim.x + 31) >> 5;
        for (int w = 0; w < nw; ++w) tot += s[w];
        g_dap[p] = sqrtf(tot);
    }
}

// ---------------------------------------------------------------------------
// Kernel B: one warp per negative row. 8 warps / block.
// Anchor staged in dynamic smem. Per-block partial sum -> g_partials.
// ---------------------------------------------------------------------------
__global__ void __launch_bounds__(256) dan_kernel(
        const float* __restrict__ anchor,
        const float* __restrict__ neg,
        int D, int R, int P) {
    extern __shared__ float4 s_a4[];           // D/4 float4 of anchor
    __shared__ float s_warp[8];

    const int D4   = D >> 2;
    const int lane = threadIdx.x & 31;
    const int wid  = threadIdx.x >> 5;

    // stage anchor into smem (vectorized)
    const float4* __restrict__ a4 = (const float4*)anchor;
    for (int i = threadIdx.x; i < D4; i += blockDim.x) s_a4[i] = a4[i];
    __syncthreads();

    const int row = blockIdx.x * 8 + wid;
    float term = 0.0f;
    if (row < R) {
        const float4* __restrict__ x4 = (const float4*)(neg + (size_t)row * D);
        float ss = 0.0f;
        #pragma unroll 4
        for (int i = lane; i < D4; i += 32) {
            float4 x = x4[i];
            float4 a = s_a4[i];
            float d0 = a.x - x.x + EPS_V;
            float d1 = a.y - x.y + EPS_V;
            float d2 = a.z - x.z + EPS_V;
            float d3 = a.w - x.w + EPS_V;
            ss = fmaf(d0, d0, ss);
            ss = fmaf(d1, d1, ss);
            ss = fmaf(d2, d2, ss);
            ss = fmaf(d3, d3, ss);
        }
        #pragma unroll
        for (int off = 16; off > 0; off >>= 1)
            ss += __shfl_xor_sync(0xffffffffu, ss, off);
        float dan = sqrtf(ss);
        float t = g_dap[row % P] - dan + MARGIN_V;
        term = t > 0.0f ? t : 0.0f;
    }
    if (lane == 0) s_warp[wid] = term;
    __syncthreads();
    if (threadIdx.x == 0) {
        float tot = 0.0f;
        #pragma unroll
        for (int w = 0; w < 8; ++w) tot += s_warp[w];
        g_partials[blockIdx.x] = tot;
    }
}

// ---------------------------------------------------------------------------
// Kernel C: deterministic final reduce of per-block partials -> d_out[0]
// ---------------------------------------------------------------------------
__global__ void __launch_bounds__(1024) reduce_kernel(float* __restrict__ out, int nPartials) {
    __shared__ float s[32];
    float acc = 0.0f;
    for (int i = threadIdx.x; i < nPartials; i += blockDim.x)
        acc += g_partials[i];
    int lane = threadIdx.x & 31;
    int wid  = threadIdx.x >> 5;
    #pragma unroll
    for (int off = 16; off > 0; off >>= 1)
        acc += __shfl_xor_sync(0xffffffffu, acc, off);
    if (lane == 0) s[wid] = acc;
    __syncthreads();
    if (threadIdx.x == 0) {
        float tot = 0.0f;
        for (int w = 0; w < 32; ++w) tot += s[w];
        out[0] = tot;
    }
}

// ---------------------------------------------------------------------------
extern "C" void kernel_launch(void* const* d_in, const int* in_sizes, int n_in,
                              void* d_out, int out_size) {
    const float* anchor = (const float*)d_in[0];
    const float* pos    = (const float*)d_in[1];
    const float* neg    = (const float*)d_in[2];
    float* out          = (float*)d_out;

    const int D = in_sizes[0];            // 2400
    const int P = in_sizes[1] / D;        // 5
    const int N = in_sizes[2] / D;        // 50000
    const int C = N / P;                  // 10000
    const int R = C * P;                  // rows actually used

    // Kernel A: d_ap
    dap_kernel<<<P, 256>>>(anchor, pos, D);

    // Kernel B: one warp per row, 8 warps per block
    const int blocksB = (R + 7) / 8;      // 6250 for the given shape
    const size_t smem = (size_t)(D >> 2) * sizeof(float4);
    dan_kernel<<<blocksB, 256, smem>>>(anchor, neg, D, R, P);

    // Kernel C: final deterministic reduce
    reduce_kernel<<<1, 1024>>>(out, blocksB);
}